// round 6
// baseline (speedup 1.0000x reference)
#include <cuda_runtime.h>
#include <math.h>

#define BB    16
#define NN    2048
#define DD    64
#define NP    512
#define NS    32
#define SCC   67
#define KS    (NS*NP)      /* 16384 */
#define GPX_N 2304         /* 32*68 sgp/sgx | samp at 2176..2243 | zeros */
#define AGG0  2176
#define EPSBN 1e-5f
#define R2    0.04f

#define OUT_PTS   (BB*3*NP)
#define OUT_LOSS  (OUT_PTS + BB*256*NP)
#define OUT_UNIQ  (OUT_LOSS + 1)

// ---------------- scratch ----------------
__device__ float g_agg [BB*NN*68];
__device__ float g_xn  [BB*NN];
__device__ int   g_idx [BB*NN*NS];
__device__ float g_h1  [BB*80*NN];
__device__ float g_h2  [BB*NP*NN];
__device__ float g_w2p [NP*80];
__device__ float g_norm[BB*NP];
__device__ float g_losspart[BB];
__device__ int   g_amax[NP];
__device__ float g_spx [(size_t)BB*NP*GPX_N];
__device__ float g_inner[(size_t)BB*NP*NP];
__device__ float g_w0p [128*144];
__device__ float g_c0  [(size_t)BB*128*KS];
__device__ float g_c1  [(size_t)BB*128*KS];
__device__ float g_mx  [(size_t)BB*256*NP];
__device__ float g_mn  [(size_t)BB*256*NP];
__device__ float g_bnm [512];
__device__ float g_bnr [512];
__device__ float g_bnp_sum[512*2048];
__device__ float g_bnp_sq [512*2048];

// ---------------- prep ----------------
__global__ void k_prep(const float* __restrict__ xyz, const float* __restrict__ pts) {
    int i = blockIdx.x * blockDim.x + threadIdx.x;
    if (i >= BB * NN) return;
    int b = i / NN, n = i % NN;
    float* arow = g_agg + (size_t)i * 68;
    const float* p = pts + (size_t)b * DD * NN + n;
#pragma unroll 8
    for (int d = 0; d < DD; d++) arow[d] = p[(size_t)d * NN];
    const float* x = xyz + (size_t)b * 3 * NN + n;
    float a = x[0], c = x[NN], e = x[2 * NN];
    arow[64] = a; arow[65] = c; arow[66] = e; arow[67] = 0.f;
    g_xn[i] = fmaf(e, e, fmaf(c, c, a * a));
}

// ---------------- ball query ----------------
__global__ void k_ballquery() {
    __shared__ float sx[NN], sy[NN], sz[NN], sn[NN];
    int b = blockIdx.y;
    int t = threadIdx.x;
    for (int j = t; j < NN; j += blockDim.x) {
        const float* a = g_agg + ((size_t)b * NN + j) * 68;
        sx[j] = a[64]; sy[j] = a[65]; sz[j] = a[66];
        sn[j] = g_xn[b * NN + j];
    }
    __syncthreads();
    int n = blockIdx.x * blockDim.x + t;
    float px = sx[n], py = sy[n], pz = sz[n], pn = sn[n];
    int base = (b * NN + n) * NS;
    int cnt = 0, first = 0;
    for (int m = 0; m < NN && cnt < NS; m++) {
        float dot = fmaf(px, sx[m], fmaf(py, sy[m], pz * sz[m]));
        float d = pn + sn[m] - 2.0f * dot;
        if (!(d > R2)) {
            if (cnt == 0) first = m;
            g_idx[base + cnt] = m;
            cnt++;
        }
    }
    for (int j = cnt; j < NS; j++) g_idx[base + j] = first;
}

// ---------------- h1 = w1 @ agg ----------------
__global__ void k_h1(const float* __restrict__ w1) {
    __shared__ float w[SCC];
    int o = blockIdx.y, b = blockIdx.z;
    if (threadIdx.x < SCC) w[threadIdx.x] = w1[o * SCC + threadIdx.x];
    __syncthreads();
    int n = blockIdx.x * blockDim.x + threadIdx.x;
    const float* arow = g_agg + ((size_t)(b * NN + n)) * 68;
    float s = 0.f;
#pragma unroll 1
    for (int c = 0; c < SCC; c++) s = fmaf(w[c], arow[c], s);
    g_h1[((size_t)b * 80 + o) * NN + n] = s;
}

// ---------------- BN stats (h1 only) ----------------
__global__ void k_bnstats(const float* __restrict__ x, int C, int Cs, int S) {
    int c = blockIdx.x, t = threadIdx.x;
    float s = 0.f, sq = 0.f;
    for (int b = 0; b < BB; b++) {
        const float* p = x + ((size_t)b * Cs + c) * S;
        for (int j = t; j < S; j += 256) { float v = p[j]; s += v; sq = fmaf(v, v, sq); }
    }
    __shared__ float rs[256], rq[256];
    rs[t] = s; rq[t] = sq; __syncthreads();
    for (int o = 128; o > 0; o >>= 1) {
        if (t < o) { rs[t] += rs[t + o]; rq[t] += rq[t + o]; }
        __syncthreads();
    }
    if (t == 0) {
        float cnt = (float)BB * (float)S;
        float m = rs[0] / cnt;
        float v = rq[0] / cnt - m * m;
        g_bnm[c] = m;
        g_bnr[c] = rsqrtf(fmaxf(v, 0.f) + EPSBN);
    }
}

// ---------------- reduce TC partial stats ----------------
__global__ void k_bnfin(int P, float count) {
    int c = blockIdx.x, t = threadIdx.x;
    float s = 0.f, sq = 0.f;
    const float* ps = g_bnp_sum + (size_t)c * 2048;
    const float* pq = g_bnp_sq  + (size_t)c * 2048;
    for (int j = t; j < P; j += 256) { s += ps[j]; sq += pq[j]; }
    __shared__ float rs[256], rq[256];
    rs[t] = s; rq[t] = sq; __syncthreads();
    for (int o = 128; o > 0; o >>= 1) {
        if (t < o) { rs[t] += rs[t + o]; rq[t] += rq[t + o]; }
        __syncthreads();
    }
    if (t == 0) {
        float m = rs[0] / count;
        float v = rq[0] / count - m * m;
        g_bnm[c] = m;
        g_bnr[c] = rsqrtf(fmaxf(v, 0.f) + EPSBN);
    }
}

// ---------------- tf32 TC GEMM: 128x256 block, 64x64 warp tiles, dbl-buffered ----------------
__device__ __forceinline__ unsigned f2tf(float v) {
    unsigned r; asm("cvt.rna.tf32.f32 %0, %1;" : "=r"(r) : "f"(v)); return r;
}

// mode 0: B row-major KxN (stride N) + optional BN/leaky per K-channel
// mode 2: spx gather: B[n,c] = agg68[(c/68<32 ? idx[n,c/68] : n)][c%68]; c/68>32 -> 0
// mode 3: conv0 edge from spx: s=col>>5,k=col&31; ch<68: sp[k*68+ch]; 68..135: sp[AGG0+ch-68]; else 0
__device__ __forceinline__ float4 ldB(
    int mode, const float* __restrict__ Bb, const int* __restrict__ idxb,
    const float* __restrict__ aggb, int N, int row, int col,
    const float* __restrict__ bnm, const float* __restrict__ bnr,
    const float* __restrict__ bng, const float* __restrict__ bnb, int bnC, int leaky)
{
    float4 v = make_float4(0.f, 0.f, 0.f, 0.f);
    if (mode == 0) {
        v = *(const float4*)&Bb[(size_t)row * N + col];
        if (bnm) {
            if (row < bnC) {
                float m = bnm[row], s = bnr[row] * bng[row], o = bnb[row];
                v.x = (v.x - m) * s + o; v.y = (v.y - m) * s + o;
                v.z = (v.z - m) * s + o; v.w = (v.w - m) * s + o;
                if (leaky) {
                    v.x = v.x > 0.f ? v.x : 0.2f * v.x;
                    v.y = v.y > 0.f ? v.y : 0.2f * v.y;
                    v.z = v.z > 0.f ? v.z : 0.2f * v.z;
                    v.w = v.w > 0.f ? v.w : 0.2f * v.w;
                }
            } else v = make_float4(0.f, 0.f, 0.f, 0.f);
        }
    } else if (mode == 2) {
        int kk = col / 68;
        int d  = col - kk * 68;
        if (kk <= 32) {
            int id = (kk < 32) ? idxb[row * NS + kk] : row;
            v = *(const float4*)&aggb[(size_t)id * 68 + d];
        }
    } else { // mode 3
        int s = col >> 5, k = col & 31, ch = row;
        const float* sp = Bb + (size_t)s * GPX_N;
        if (ch < 68) {
            v.x = sp[(k + 0) * 68 + ch];
            v.y = sp[(k + 1) * 68 + ch];
            v.z = sp[(k + 2) * 68 + ch];
            v.w = sp[(k + 3) * 68 + ch];
        } else if (ch < 136) {
            float w = sp[AGG0 + ch - 68];
            v = make_float4(w, w, w, w);
        }
    }
    return v;
}

__global__ __launch_bounds__(256) void k_gemm_tc(
    const float* __restrict__ A, const float* __restrict__ B, float* __restrict__ C,
    int M, int N, int K, size_t sA, size_t sB, size_t sC,
    int mode, int bT, int tri,
    const int* __restrict__ idxg, const float* __restrict__ aggg,
    const float* __restrict__ bnm, const float* __restrict__ bnr,
    const float* __restrict__ bng, const float* __restrict__ bnb, int bnC, int leaky,
    float* __restrict__ bnp_sum, float* __restrict__ bnp_sq,
    float* __restrict__ mxp, float* __restrict__ mnp)
{
    __shared__ unsigned As[2][8][136];
    __shared__ unsigned Bs[2][8][264];
    __shared__ float ssum[8][64];
    __shared__ float ssq [8][64];
    const float* Ab = A + blockIdx.z * sA;
    const float* Bb = B + blockIdx.z * sB;
    const int*   idxb = idxg + (size_t)blockIdx.z * NN * NS;
    const float* aggb = aggg + (size_t)blockIdx.z * NN * 68;
    int t = threadIdx.x, lane = t & 31, wid = t >> 5;
    int g = lane >> 2, tid4 = lane & 3;
    int wm = (wid & 1) * 64, wn = (wid >> 1) * 64;
    int row0, col0;
    if (tri) {
        const int TI[6] = {0,0,1,1,2,3};
        const int TJ[6] = {0,1,0,1,1,1};
        row0 = TI[blockIdx.x] * 128; col0 = TJ[blockIdx.x] * 256;
    } else {
        row0 = blockIdx.y * 128; col0 = blockIdx.x * 256;
    }

    float acc[4][8][4];
#pragma unroll
    for (int i = 0; i < 4; i++)
#pragma unroll
        for (int j = 0; j < 8; j++)
#pragma unroll
            for (int r = 0; r < 4; r++) acc[i][j][r] = 0.f;

    // per-thread load/store indices
    int arow = t >> 1, akk = (t & 1) * 4;          // A: 1 float4
    int bro0 = t >> 6, bco = (t & 63) * 4;         // B normal: 2 float4
    int bro1 = bro0 + 4;
    int brT0 = t >> 1, bkT = (t & 1) * 4;          // B transposed: 2 float4
    int brT1 = brT0 + 128;

    float4 ra, rb0, rb1;

#define GLD(k0) { \
    ra = *(const float4*)&Ab[(size_t)(row0 + arow) * K + (k0) + akk]; \
    if (bT) { \
        rb0 = *(const float4*)&Bb[(size_t)(col0 + brT0) * K + (k0) + bkT]; \
        rb1 = *(const float4*)&Bb[(size_t)(col0 + brT1) * K + (k0) + bkT]; \
    } else { \
        rb0 = ldB(mode, Bb, idxb, aggb, N, (k0) + bro0, col0 + bco, bnm, bnr, bng, bnb, bnC, leaky); \
        rb1 = ldB(mode, Bb, idxb, aggb, N, (k0) + bro1, col0 + bco, bnm, bnr, bng, bnb, bnC, leaky); \
    } }

#define SST(bf_) { \
    As[bf_][akk+0][arow] = f2tf(ra.x); As[bf_][akk+1][arow] = f2tf(ra.y); \
    As[bf_][akk+2][arow] = f2tf(ra.z); As[bf_][akk+3][arow] = f2tf(ra.w); \
    if (bT) { \
        Bs[bf_][bkT+0][brT0] = f2tf(rb0.x); Bs[bf_][bkT+1][brT0] = f2tf(rb0.y); \
        Bs[bf_][bkT+2][brT0] = f2tf(rb0.z); Bs[bf_][bkT+3][brT0] = f2tf(rb0.w); \
        Bs[bf_][bkT+0][brT1] = f2tf(rb1.x); Bs[bf_][bkT+1][brT1] = f2tf(rb1.y); \
        Bs[bf_][bkT+2][brT1] = f2tf(rb1.z); Bs[bf_][bkT+3][brT1] = f2tf(rb1.w); \
    } else { \
        uint4 u0 = make_uint4(f2tf(rb0.x), f2tf(rb0.y), f2tf(rb0.z), f2tf(rb0.w)); \
        uint4 u1 = make_uint4(f2tf(rb1.x), f2tf(rb1.y), f2tf(rb1.z), f2tf(rb1.w)); \
        *(uint4*)&Bs[bf_][bro0][bco] = u0; \
        *(uint4*)&Bs[bf_][bro1][bco] = u1; \
    } }

    GLD(0);
    SST(0);
    __syncthreads();

    int buf = 0;
    for (int k0 = 0; k0 < K; k0 += 8) {
        int more = (k0 + 8) < K;
        if (more) GLD(k0 + 8);

        unsigned af[4][4], bf[8][2];
#pragma unroll
        for (int mf = 0; mf < 4; mf++) {
            int mb = wm + mf * 16 + g;
            af[mf][0] = As[buf][tid4][mb];
            af[mf][1] = As[buf][tid4][mb + 8];
            af[mf][2] = As[buf][tid4 + 4][mb];
            af[mf][3] = As[buf][tid4 + 4][mb + 8];
        }
#pragma unroll
        for (int nf = 0; nf < 8; nf++) {
            int nb = wn + nf * 8 + g;
            bf[nf][0] = Bs[buf][tid4][nb];
            bf[nf][1] = Bs[buf][tid4 + 4][nb];
        }
#pragma unroll
        for (int mf = 0; mf < 4; mf++)
#pragma unroll
            for (int nf = 0; nf < 8; nf++) {
                asm volatile(
                    "mma.sync.aligned.m16n8k8.row.col.f32.tf32.tf32.f32 "
                    "{%0,%1,%2,%3}, {%4,%5,%6,%7}, {%8,%9}, {%0,%1,%2,%3};"
                    : "+f"(acc[mf][nf][0]), "+f"(acc[mf][nf][1]),
                      "+f"(acc[mf][nf][2]), "+f"(acc[mf][nf][3])
                    : "r"(af[mf][0]), "r"(af[mf][1]), "r"(af[mf][2]), "r"(af[mf][3]),
                      "r"(bf[nf][0]), "r"(bf[nf][1]));
            }

        if (more) SST(buf ^ 1);
        __syncthreads();
        buf ^= 1;
    }

    if (C) {
        float* Cb = C + blockIdx.z * sC;
#pragma unroll
        for (int mf = 0; mf < 4; mf++) {
#pragma unroll
            for (int nf = 0; nf < 8; nf++) {
                size_t r0 = (size_t)(row0 + wm + mf * 16 + g);
                int c = col0 + wn + nf * 8 + tid4 * 2;
                *(float2*)&Cb[r0 * N + c]       = make_float2(acc[mf][nf][0], acc[mf][nf][1]);
                *(float2*)&Cb[(r0 + 8) * N + c] = make_float2(acc[mf][nf][2], acc[mf][nf][3]);
            }
        }
    }

    if (mxp) {
        int sbase = (col0 + wn) >> 5;
#pragma unroll
        for (int mf = 0; mf < 4; mf++) {
#pragma unroll
            for (int h = 0; h < 2; h++) {
                float M0 = -1e30f, m0 = 1e30f, M1 = -1e30f, m1 = 1e30f;
#pragma unroll
                for (int nf = h * 4; nf < h * 4 + 4; nf++) {
                    M0 = fmaxf(M0, fmaxf(acc[mf][nf][0], acc[mf][nf][1]));
                    m0 = fminf(m0, fminf(acc[mf][nf][0], acc[mf][nf][1]));
                    M1 = fmaxf(M1, fmaxf(acc[mf][nf][2], acc[mf][nf][3]));
                    m1 = fminf(m1, fminf(acc[mf][nf][2], acc[mf][nf][3]));
                }
                M0 = fmaxf(M0, __shfl_xor_sync(~0u, M0, 1)); M0 = fmaxf(M0, __shfl_xor_sync(~0u, M0, 2));
                m0 = fminf(m0, __shfl_xor_sync(~0u, m0, 1)); m0 = fminf(m0, __shfl_xor_sync(~0u, m0, 2));
                M1 = fmaxf(M1, __shfl_xor_sync(~0u, M1, 1)); M1 = fmaxf(M1, __shfl_xor_sync(~0u, M1, 2));
                m1 = fminf(m1, __shfl_xor_sync(~0u, m1, 1)); m1 = fminf(m1, __shfl_xor_sync(~0u, m1, 2));
                if (tid4 == 0) {
                    int r = row0 + wm + mf * 16 + g;
                    size_t o1 = ((size_t)blockIdx.z * M + r) * (N >> 5) + sbase + h;
                    size_t o2 = ((size_t)blockIdx.z * M + r + 8) * (N >> 5) + sbase + h;
                    mxp[o1] = M0; mnp[o1] = m0;
                    mxp[o2] = M1; mnp[o2] = m1;
                }
            }
        }
    }

    if (bnp_sum) {
#pragma unroll
        for (int mf = 0; mf < 4; mf++) {
            float s0 = 0.f, q0 = 0.f, s1 = 0.f, q1 = 0.f;
#pragma unroll
            for (int nf = 0; nf < 8; nf++) {
                float a = acc[mf][nf][0], b = acc[mf][nf][1];
                float c = acc[mf][nf][2], d = acc[mf][nf][3];
                s0 += a + b; q0 += a * a + b * b;
                s1 += c + d; q1 += c * c + d * d;
            }
            s0 += __shfl_xor_sync(~0u, s0, 1); s0 += __shfl_xor_sync(~0u, s0, 2);
            q0 += __shfl_xor_sync(~0u, q0, 1); q0 += __shfl_xor_sync(~0u, q0, 2);
            s1 += __shfl_xor_sync(~0u, s1, 1); s1 += __shfl_xor_sync(~0u, s1, 2);
            q1 += __shfl_xor_sync(~0u, q1, 1); q1 += __shfl_xor_sync(~0u, q1, 2);
            if (tid4 == 0) {
                ssum[wid][mf * 16 + g] = s0;     ssq[wid][mf * 16 + g] = q0;
                ssum[wid][mf * 16 + g + 8] = s1; ssq[wid][mf * 16 + g + 8] = q1;
            }
        }
        __syncthreads();
        if (t < 128) {
            int half = t >> 6, lr = t & 63;
            float s = ssum[half][lr] + ssum[half + 2][lr]
                    + ssum[half + 4][lr] + ssum[half + 6][lr];
            float q = ssq[half][lr] + ssq[half + 2][lr]
                    + ssq[half + 4][lr] + ssq[half + 6][lr];
            int ch = row0 + t;
            int slot = (int)(blockIdx.z * gridDim.x + blockIdx.x);
            bnp_sum[(size_t)ch * 2048 + slot] = s;
            bnp_sq [(size_t)ch * 2048 + slot] = q;
        }
    }
#undef GLD
#undef SST
}

// ---------------- softmax (fused BN2 affine) ----------------
__global__ void k_softmax(const float* __restrict__ g2, const float* __restrict__ b2) {
    int row = blockIdx.x;
    int s = row & (NP - 1);
    float mch = g_bnm[s], rch = g_bnr[s] * g2[s], bch = b2[s];
    float* x = g_h2 + (size_t)row * NN;
    int t = threadIdx.x;
    __shared__ float rs[256], rq[256];
    float m = -1e30f;
    for (int j = t; j < NN; j += 256) {
        float v = (x[j] - mch) * rch + bch;
        m = fmaxf(m, v);
    }
    rs[t] = m; __syncthreads();
    for (int o = 128; o > 0; o >>= 1) { if (t < o) rs[t] = fmaxf(rs[t], rs[t + o]); __syncthreads(); }
    m = rs[0]; __syncthreads();
    float ssum = 0.f, sq = 0.f;
    for (int j = t; j < NN; j += 256) {
        float v = (x[j] - mch) * rch + bch;
        float e = expf(v - m);
        x[j] = e;
        ssum += e; sq = fmaf(e, e, sq);
    }
    rs[t] = ssum; rq[t] = sq; __syncthreads();
    for (int o = 128; o > 0; o >>= 1) { if (t < o) { rs[t] += rs[t + o]; rq[t] += rq[t + o]; } __syncthreads(); }
    ssum = rs[0]; sq = rq[0];
    float inv = 1.f / ssum;
    for (int j = t; j < NN; j += 256) x[j] *= inv;
    if (t == 0) g_norm[row] = sqrtf(sq) * inv;
}

// ---------------- argmax + unique ----------------
__global__ void k_argmax() {
    int sidx = blockIdx.x;
    const float* x = g_h2 + (size_t)sidx * NN;
    int t = threadIdx.x;
    float bv = -1e30f; int bi = NN;
    for (int j = t; j < NN; j += 256) { float v = x[j]; if (v > bv) { bv = v; bi = j; } }
    __shared__ float rv[256]; __shared__ int ri[256];
    rv[t] = bv; ri[t] = bi; __syncthreads();
    for (int o = 128; o > 0; o >>= 1) {
        if (t < o) {
            if (rv[t + o] > rv[t] || (rv[t + o] == rv[t] && ri[t + o] < ri[t])) {
                rv[t] = rv[t + o]; ri[t] = ri[t + o];
            }
        }
        __syncthreads();
    }
    if (t == 0) g_amax[sidx] = ri[0];
}

__global__ void k_unique(float* __restrict__ out, int out_size) {
    __shared__ int fl[NN];
    __shared__ int rc[256];
    int t = threadIdx.x;
    for (int j = t; j < NN; j += 256) fl[j] = 0;
    __syncthreads();
    for (int s = t; s < NP; s += 256) fl[g_amax[s]] = 1;
    __syncthreads();
    int c = 0;
    for (int j = t; j < NN; j += 256) c += fl[j];
    rc[t] = c; __syncthreads();
    for (int o = 128; o > 0; o >>= 1) { if (t < o) rc[t] += rc[t + o]; __syncthreads(); }
    if (t == 0 && OUT_UNIQ < out_size) out[OUT_UNIQ] = (float)rc[0];
}

// ---------------- cos loss (upper triangle only, x2) ----------------
__global__ void k_loss() {
    int b = blockIdx.x;
    int t = threadIdx.x;
    const float* inn = g_inner + (size_t)b * NP * NP;
    const float* nrm = g_norm + b * NP;
    float s = 0.f;
    for (int i = t; i < NP * NP; i += 256) {
        int ss = i >> 9, tt = i & (NP - 1);
        if (tt <= ss) continue;
        float v = inn[i] / (nrm[ss] * nrm[tt] + 1e-10f);
        s = fmaf(2.f * v, v, s);
    }
    __shared__ float red[256];
    red[t] = s; __syncthreads();
    for (int o = 128; o > 0; o >>= 1) { if (t < o) red[t] += red[t + o]; __syncthreads(); }
    if (t == 0) g_losspart[b] = red[0];
}

__global__ void k_lossfin(float* __restrict__ out, int out_size) {
    if (threadIdx.x == 0 && OUT_LOSS < out_size) {
        float acc = 0.f;
        for (int b = 0; b < BB; b++) acc += sqrtf(g_losspart[b]);
        out[OUT_LOSS] = acc / (float)BB;
    }
}

// ---------------- weight prep ----------------
__global__ void k_w2p(const float* __restrict__ w2) {
    int i = blockIdx.x * blockDim.x + threadIdx.x;
    if (i >= NP * 80) return;
    int o = i / 80, c = i % 80;
    g_w2p[i] = (c < SCC) ? w2[o * SCC + c] : 0.f;
}

__global__ void k_padw(const float* __restrict__ w) {
    int i = blockIdx.x * blockDim.x + threadIdx.x;
    if (i >= 128 * 144) return;
    int o = i / 144, ch = i % 144;
    const float* wr = w + o * 134;
    float v = 0.f;
    if (ch < 64)       v = wr[64 + ch];
    else if (ch < 67)  v = wr[131 + (ch - 64)];
    else if (ch == 67) v = 0.f;
    else if (ch < 132) { int c = ch - 68;  v = wr[c] - wr[64 + c]; }
    else if (ch < 135) { int c = ch - 132; v = wr[128 + c] - wr[131 + c]; }
    g_w0p[i] = v;
}

// ---------------- final: BN + leaky on max/min, pick true max ----------------
__global__ void k_bn_max(const float* __restrict__ g2, const float* __restrict__ b2,
                         float* __restrict__ out, int out_size) {
    int i = blockIdx.x * blockDim.x + threadIdx.x;
    if (i >= BB * 256 * NP) return;
    int o = (i / NP) % 256;
    float mch = g_bnm[o], rch = g_bnr[o] * g2[o], bch = b2[o];
    float v1 = (g_mx[i] - mch) * rch + bch;
    float v2 = (g_mn[i] - mch) * rch + bch;
    v1 = v1 > 0.f ? v1 : 0.2f * v1;
    v2 = v2 > 0.f ? v2 : 0.2f * v2;
    int oi = OUT_PTS + i;
    if (oi < out_size) out[oi] = fmaxf(v1, v2);
}

__global__ void k_wxyz(float* __restrict__ out, int out_size) {
    int i = blockIdx.x * blockDim.x + threadIdx.x;
    if (i >= BB * 3 * NP) return;
    int s = i % NP; int c = (i / NP) % 3; int b = i / (3 * NP);
    if (i < out_size) out[i] = g_spx[((size_t)b * NP + s) * GPX_N + AGG0 + 64 + c];
}

// ---------------- launch ----------------
extern "C" void kernel_launch(void* const* d_in, const int* in_sizes, int n_in,
                              void* d_out, int out_size) {
    const float* xyz   = (const float*)d_in[0];
    const float* pts   = (const float*)d_in[1];
    const float* w1_w  = (const float*)d_in[2];
    const float* bn1_g = (const float*)d_in[4];
    const float* bn1_b = (const float*)d_in[5];
    const float* w2_w  = (const float*)d_in[6];
    const float* bn2_g = (const float*)d_in[8];
    const float* bn2_b = (const float*)d_in[9];
    const float* c0w   = (const float*)d_in[10];
    const float* bg0   = (const float*)d_in[12];
    const float* bb0   = (const float*)d_in[13];
    const float* c1w   = (const float*)d_in[14];
    const float* bg1   = (const float*)d_in[16];
    const float* bb1   = (const float*)d_in[17];
    const float* c2w   = (const float*)d_in[18];
    const float* bg2   = (const float*)d_in[20];
    const float* bb2   = (const float*)d_in[21];
    float* out = (float*)d_out;

    float *p_agg, *p_h1, *p_h2, *p_w2p, *p_spx, *p_inner, *p_w0p,
          *p_c0, *p_c1, *p_mx, *p_mn, *p_bnm, *p_bnr, *p_bps, *p_bpq;
    int* p_idx;
    cudaGetSymbolAddress((void**)&p_agg,   g_agg);
    cudaGetSymbolAddress((void**)&p_idx,   g_idx);
    cudaGetSymbolAddress((void**)&p_h1,    g_h1);
    cudaGetSymbolAddress((void**)&p_h2,    g_h2);
    cudaGetSymbolAddress((void**)&p_w2p,   g_w2p);
    cudaGetSymbolAddress((void**)&p_spx,   g_spx);
    cudaGetSymbolAddress((void**)&p_inner, g_inner);
    cudaGetSymbolAddress((void**)&p_w0p,   g_w0p);
    cudaGetSymbolAddress((void**)&p_c0,    g_c0);
    cudaGetSymbolAddress((void**)&p_c1,    g_c1);
    cudaGetSymbolAddress((void**)&p_mx,    g_mx);
    cudaGetSymbolAddress((void**)&p_mn,    g_mn);
    cudaGetSymbolAddress((void**)&p_bnm,   g_bnm);
    cudaGetSymbolAddress((void**)&p_bnr,   g_bnr);
    cudaGetSymbolAddress((void**)&p_bps,   g_bnp_sum);
    cudaGetSymbolAddress((void**)&p_bpq,   g_bnp_sq);

    k_prep<<<(BB * NN + 255) / 256, 256>>>(xyz, pts);
    k_ballquery<<<dim3(NN / 256, BB), 256>>>();
    k_h1<<<dim3(NN / 256, SCC, BB), 256>>>(w1_w);
    k_bnstats<<<SCC, 256>>>(p_h1, SCC, 80, NN);
    k_w2p<<<(NP * 80 + 255) / 256, 256>>>(w2_w);
    // h2 = w2p @ bn1(h1)  (TC tf32, K=80; BN on B; stats epilogue for bn2)
    k_gemm_tc<<<dim3(NN / 256, 4, BB), 256>>>(
        p_w2p, p_h1, p_h2, NP, NN, 80,
        0, (size_t)80 * NN, (size_t)NP * NN,
        0, 0, 0, p_idx, p_agg,
        p_bnm, p_bnr, bn1_g, bn1_b, SCC, 0,
        p_bps, p_bpq, nullptr, nullptr);
    k_bnfin<<<NP, 256>>>(BB * (NN / 256), (float)BB * NN);
    k_softmax<<<BB * NP, 256>>>(bn2_g, bn2_b);
    k_argmax<<<NP, 256>>>();
    k_unique<<<1, 256>>>(out, out_size);
    // inner = sel @ sel^T  (TC NT, upper-tri 128x256 blocks)
    k_gemm_tc<<<dim3(6, 1, BB), 256>>>(
        p_h2, p_h2, p_inner, NP, NP, NN,
        (size_t)NP * NN, (size_t)NP * NN, (size_t)NP * NP,
        0, 1, 1, p_idx, p_agg,
        nullptr, nullptr, nullptr, nullptr, 0, 0,
        nullptr, nullptr, nullptr, nullptr);
    k_loss<<<BB, 256>>>();
    k_lossfin<<<1, 1>>>(out, out_size);
    // spx = sel @ gather(agg)  (TC mode2)
    k_gemm_tc<<<dim3(GPX_N / 256, 4, BB), 256>>>(
        p_h2, nullptr, p_spx, NP, GPX_N, NN,
        (size_t)NP * NN, 0, (size_t)NP * GPX_N,
        2, 0, 0, p_idx, p_agg,
        nullptr, nullptr, nullptr, nullptr, 0, 0,
        nullptr, nullptr, nullptr, nullptr);
    k_padw<<<(128 * 144 + 255) / 256, 256>>>(c0w);
    // conv0  (TC mode3: edge synthesized from spx; stats epilogue)
    k_gemm_tc<<<dim3(KS / 256, 1, BB), 256>>>(
        p_w0p, p_spx, p_c0, 128, KS, 144,
        0, (size_t)NP * GPX_N, (size_t)128 * KS,
        3, 0, 0, p_idx, p_agg,
        nullptr, nullptr, nullptr, nullptr, 0, 0,
        p_bps, p_bpq, nullptr, nullptr);
    k_bnfin<<<128, 256>>>(BB * (KS / 256), (float)BB * KS);
    // conv1 (BN0+leaky fused on B, stats epilogue)
    k_gemm_tc<<<dim3(KS / 256, 1, BB), 256>>>(
        c1w, p_c0, p_c1, 128, KS, 128,
        0, (size_t)128 * KS, (size_t)128 * KS,
        0, 0, 0, p_idx, p_agg,
        p_bnm, p_bnr, bg0, bb0, 128, 1,
        p_bps, p_bpq, nullptr, nullptr);
    k_bnfin<<<128, 256>>>(BB * (KS / 256), (float)BB * KS);
    // conv2 (BN1+leaky fused on B, stats + maxmin epilogues, no C store)
    k_gemm_tc<<<dim3(KS / 256, 2, BB), 256>>>(
        c2w, p_c1, nullptr, 256, KS, 128,
        0, (size_t)128 * KS, 0,
        0, 0, 0, p_idx, p_agg,
        p_bnm, p_bnr, bg1, bb1, 128, 1,
        p_bps, p_bpq, p_mx, p_mn);
    k_bnfin<<<256, 256>>>(BB * (KS / 256), (float)BB * KS);
    k_bn_max<<<(BB * 256 * NP + 255) / 256, 256>>>(bg2, bb2, out, out_size);
    k_wxyz<<<(BB * 3 * NP + 255) / 256, 256>>>(out, out_size);
}

// round 7
// speedup vs baseline: 1.3670x; 1.3670x over previous
#include <cuda_runtime.h>
#include <math.h>

#define BB    16
#define NN    2048
#define DD    64
#define NP    512
#define NS    32
#define SCC   67
#define KS    (NS*NP)      /* 16384 */
#define GPX_N 2304         /* 32*68 sgp/sgx | samp at 2176..2243 | zeros */
#define AGG0  2176
#define EPSBN 1e-5f
#define R2    0.04f

#define OUT_PTS   (BB*3*NP)
#define OUT_LOSS  (OUT_PTS + BB*256*NP)
#define OUT_UNIQ  (OUT_LOSS + 1)

// ---------------- scratch ----------------
__device__ float g_agg [BB*NN*68];
__device__ float g_xn  [BB*NN];
__device__ int   g_idx [BB*NN*NS];
__device__ float g_h1  [BB*80*NN];
__device__ float g_h2  [BB*NP*NN];
__device__ float g_w2p [NP*80];
__device__ float g_norm[BB*NP];
__device__ float g_losspart[BB];
__device__ int   g_amax[NP];
__device__ float g_spx [(size_t)BB*NP*GPX_N];
__device__ float g_inner[(size_t)BB*NP*NP];
__device__ float g_w0p [128*144];
__device__ float g_c0  [(size_t)BB*128*KS];
__device__ float g_c1  [(size_t)BB*128*KS];
__device__ float g_mx  [(size_t)BB*256*NP];
__device__ float g_mn  [(size_t)BB*256*NP];
__device__ float g_bnm [512];
__device__ float g_bnr [512];
__device__ float g_bnp_sum[512*2048];
__device__ float g_bnp_sq [512*2048];

// ---------------- prep ----------------
__global__ void k_prep(const float* __restrict__ xyz, const float* __restrict__ pts) {
    int i = blockIdx.x * blockDim.x + threadIdx.x;
    if (i >= BB * NN) return;
    int b = i / NN, n = i % NN;
    float* arow = g_agg + (size_t)i * 68;
    const float* p = pts + (size_t)b * DD * NN + n;
#pragma unroll 8
    for (int d = 0; d < DD; d++) arow[d] = p[(size_t)d * NN];
    const float* x = xyz + (size_t)b * 3 * NN + n;
    float a = x[0], c = x[NN], e = x[2 * NN];
    arow[64] = a; arow[65] = c; arow[66] = e; arow[67] = 0.f;
    g_xn[i] = fmaf(e, e, fmaf(c, c, a * a));
}

// ---------------- ball query ----------------
__global__ void k_ballquery() {
    __shared__ float sx[NN], sy[NN], sz[NN], sn[NN];
    int b = blockIdx.y;
    int t = threadIdx.x;
    for (int j = t; j < NN; j += blockDim.x) {
        const float* a = g_agg + ((size_t)b * NN + j) * 68;
        sx[j] = a[64]; sy[j] = a[65]; sz[j] = a[66];
        sn[j] = g_xn[b * NN + j];
    }
    __syncthreads();
    int n = blockIdx.x * blockDim.x + t;
    float px = sx[n], py = sy[n], pz = sz[n], pn = sn[n];
    int base = (b * NN + n) * NS;
    int cnt = 0, first = 0;
    for (int m = 0; m < NN && cnt < NS; m++) {
        float dot = fmaf(px, sx[m], fmaf(py, sy[m], pz * sz[m]));
        float d = pn + sn[m] - 2.0f * dot;
        if (!(d > R2)) {
            if (cnt == 0) first = m;
            g_idx[base + cnt] = m;
            cnt++;
        }
    }
    for (int j = cnt; j < NS; j++) g_idx[base + j] = first;
}

// ---------------- h1 = w1 @ agg ----------------
__global__ void k_h1(const float* __restrict__ w1) {
    __shared__ float w[SCC];
    int o = blockIdx.y, b = blockIdx.z;
    if (threadIdx.x < SCC) w[threadIdx.x] = w1[o * SCC + threadIdx.x];
    __syncthreads();
    int n = blockIdx.x * blockDim.x + threadIdx.x;
    const float* arow = g_agg + ((size_t)(b * NN + n)) * 68;
    float s = 0.f;
#pragma unroll 1
    for (int c = 0; c < SCC; c++) s = fmaf(w[c], arow[c], s);
    g_h1[((size_t)b * 80 + o) * NN + n] = s;
}

// ---------------- BN stats (h1 only) ----------------
__global__ void k_bnstats(const float* __restrict__ x, int C, int Cs, int S) {
    int c = blockIdx.x, t = threadIdx.x;
    float s = 0.f, sq = 0.f;
    for (int b = 0; b < BB; b++) {
        const float* p = x + ((size_t)b * Cs + c) * S;
        for (int j = t; j < S; j += 256) { float v = p[j]; s += v; sq = fmaf(v, v, sq); }
    }
    __shared__ float rs[256], rq[256];
    rs[t] = s; rq[t] = sq; __syncthreads();
    for (int o = 128; o > 0; o >>= 1) {
        if (t < o) { rs[t] += rs[t + o]; rq[t] += rq[t + o]; }
        __syncthreads();
    }
    if (t == 0) {
        float cnt = (float)BB * (float)S;
        float m = rs[0] / cnt;
        float v = rq[0] / cnt - m * m;
        g_bnm[c] = m;
        g_bnr[c] = rsqrtf(fmaxf(v, 0.f) + EPSBN);
    }
}

// ---------------- reduce TC partial stats ----------------
__global__ void k_bnfin(int P, float count) {
    int c = blockIdx.x, t = threadIdx.x;
    float s = 0.f, sq = 0.f;
    const float* ps = g_bnp_sum + (size_t)c * 2048;
    const float* pq = g_bnp_sq  + (size_t)c * 2048;
    for (int j = t; j < P; j += 256) { s += ps[j]; sq += pq[j]; }
    __shared__ float rs[256], rq[256];
    rs[t] = s; rq[t] = sq; __syncthreads();
    for (int o = 128; o > 0; o >>= 1) {
        if (t < o) { rs[t] += rs[t + o]; rq[t] += rq[t + o]; }
        __syncthreads();
    }
    if (t == 0) {
        float m = rs[0] / count;
        float v = rq[0] / count - m * m;
        g_bnm[c] = m;
        g_bnr[c] = rsqrtf(fmaxf(v, 0.f) + EPSBN);
    }
}

// ---------------- tf32 TC GEMM (R5-proven 128x128 config) ----------------
__device__ __forceinline__ unsigned f2tf(float v) {
    unsigned r; asm("cvt.rna.tf32.f32 %0, %1;" : "=r"(r) : "f"(v)); return r;
}

// mode 0: B row-major KxN (+optional BN/leaky per K-channel)
// mode 2: spx-gather: B[n,c] = agg68[(c/68<32 ? idx[n,c/68] : n)][c%68]; c/68>32 -> 0
// mode 3: conv0-edge: s=col>>5,k=col&31; ch<68: sp[k*68+ch]; 68..135: sp[AGG0+ch-68]; else 0
__device__ __forceinline__ float4 ldB(
    int mode, const float* __restrict__ Bb, const int* __restrict__ idxb,
    const float* __restrict__ aggb, int N, int row, int col,
    const float* __restrict__ bnm, const float* __restrict__ bnr,
    const float* __restrict__ bng, const float* __restrict__ bnb, int bnC, int leaky)
{
    float4 v = make_float4(0.f, 0.f, 0.f, 0.f);
    if (mode == 0) {
        v = *(const float4*)&Bb[(size_t)row * N + col];
        if (bnm) {
            if (row < bnC) {
                float m = bnm[row], s = bnr[row] * bng[row], o = bnb[row];
                v.x = (v.x - m) * s + o; v.y = (v.y - m) * s + o;
                v.z = (v.z - m) * s + o; v.w = (v.w - m) * s + o;
                if (leaky) {
                    v.x = v.x > 0.f ? v.x : 0.2f * v.x;
                    v.y = v.y > 0.f ? v.y : 0.2f * v.y;
                    v.z = v.z > 0.f ? v.z : 0.2f * v.z;
                    v.w = v.w > 0.f ? v.w : 0.2f * v.w;
                }
            } else v = make_float4(0.f, 0.f, 0.f, 0.f);
        }
    } else if (mode == 2) {
        int kk = col / 68;
        int d  = col - kk * 68;
        if (kk <= 32) {
            int id = (kk < 32) ? idxb[row * NS + kk] : row;
            v = *(const float4*)&aggb[(size_t)id * 68 + d];
        }
    } else { // mode 3
        int s = col >> 5, k = col & 31, ch = row;
        const float* sp = Bb + (size_t)s * GPX_N;
        if (ch < 68) {
            v.x = sp[(k + 0) * 68 + ch];
            v.y = sp[(k + 1) * 68 + ch];
            v.z = sp[(k + 2) * 68 + ch];
            v.w = sp[(k + 3) * 68 + ch];
        } else if (ch < 136) {
            float w = sp[AGG0 + ch - 68];
            v = make_float4(w, w, w, w);
        }
    }
    return v;
}

#define TC_LD(k0) { \
    ra0 = *(const float4*)&Ab[(size_t)(row0+ar0)*K + (k0) + ak0]; \
    ra1 = *(const float4*)&Ab[(size_t)(row0+ar1)*K + (k0) + ak1]; \
    if (bT) { \
        rb0 = *(const float4*)&Bb[(size_t)(col0+ar0)*K + (k0) + ak0]; \
        rb1 = *(const float4*)&Bb[(size_t)(col0+ar1)*K + (k0) + ak1]; \
    } else { \
        rb0 = ldB(mode, Bb, idxb, aggb, N, (k0)+br0, col0+bc0, bnm, bnr, bng, bnb, bnC, leaky); \
        rb1 = ldB(mode, Bb, idxb, aggb, N, (k0)+br1, col0+bc1, bnm, bnr, bng, bnb, bnC, leaky); \
    } }

#define TC_ST() { \
    As[ak0+0][ar0]=f2tf(ra0.x); As[ak0+1][ar0]=f2tf(ra0.y); As[ak0+2][ar0]=f2tf(ra0.z); As[ak0+3][ar0]=f2tf(ra0.w); \
    As[ak1+0][ar1]=f2tf(ra1.x); As[ak1+1][ar1]=f2tf(ra1.y); As[ak1+2][ar1]=f2tf(ra1.z); As[ak1+3][ar1]=f2tf(ra1.w); \
    if (bT) { \
        Bs[ak0+0][ar0]=f2tf(rb0.x); Bs[ak0+1][ar0]=f2tf(rb0.y); Bs[ak0+2][ar0]=f2tf(rb0.z); Bs[ak0+3][ar0]=f2tf(rb0.w); \
        Bs[ak1+0][ar1]=f2tf(rb1.x); Bs[ak1+1][ar1]=f2tf(rb1.y); Bs[ak1+2][ar1]=f2tf(rb1.z); Bs[ak1+3][ar1]=f2tf(rb1.w); \
    } else { \
        uint4 u0 = make_uint4(f2tf(rb0.x), f2tf(rb0.y), f2tf(rb0.z), f2tf(rb0.w)); \
        uint4 u1 = make_uint4(f2tf(rb1.x), f2tf(rb1.y), f2tf(rb1.z), f2tf(rb1.w)); \
        *(uint4*)&Bs[br0][bc0] = u0; \
        *(uint4*)&Bs[br1][bc1] = u1; \
    } }

__global__ __launch_bounds__(256, 2) void k_gemm_tc(
    const float* __restrict__ A, const float* __restrict__ B, float* __restrict__ C,
    int M, int N, int K, size_t sA, size_t sB, size_t sC,
    int mode, int bT, int tri,
    const int* __restrict__ idxg, const float* __restrict__ aggg,
    const float* __restrict__ bnm, const float* __restrict__ bnr,
    const float* __restrict__ bng, const float* __restrict__ bnb, int bnC, int leaky,
    float* __restrict__ bnp_sum, float* __restrict__ bnp_sq,
    float* __restrict__ mxp, float* __restrict__ mnp)
{
    __shared__ unsigned As[16][136];
    __shared__ unsigned Bs[16][136];
    __shared__ float ssum[8][64];
    __shared__ float ssq [8][64];
    const float* Ab = A + blockIdx.z * sA;
    const float* Bb = B + blockIdx.z * sB;
    const int*   idxb = idxg + (size_t)blockIdx.z * NN * NS;
    const float* aggb = aggg + (size_t)blockIdx.z * NN * 68;
    int t = threadIdx.x, lane = t & 31, wid = t >> 5;
    int g = lane >> 2, tid4 = lane & 3;
    int wm = (wid >> 2) * 64, wn = (wid & 3) * 32;
    int row0, col0;
    if (tri) {
        const int TI[10] = {0,0,0,0,1,1,1,2,2,3};
        const int TJ[10] = {0,1,2,3,1,2,3,2,3,3};
        row0 = TI[blockIdx.x] * 128; col0 = TJ[blockIdx.x] * 128;
    } else {
        row0 = blockIdx.y * 128; col0 = blockIdx.x * 128;
    }

    float acc[4][4][4];
#pragma unroll
    for (int i = 0; i < 4; i++)
#pragma unroll
        for (int j = 0; j < 4; j++)
#pragma unroll
            for (int r = 0; r < 4; r++) acc[i][j][r] = 0.f;

    int l0 = t, l1 = t + 256;
    int ar0 = l0 >> 2, ak0 = (l0 & 3) * 4;
    int ar1 = l1 >> 2, ak1 = (l1 & 3) * 4;
    int br0 = l0 >> 5, bc0 = (l0 & 31) * 4;
    int br1 = l1 >> 5, bc1 = (l1 & 31) * 4;

    float4 ra0, ra1, rb0, rb1;

    TC_LD(0);
    TC_ST();
    __syncthreads();

    for (int k0 = 0; k0 < K; k0 += 16) {
        int more = (k0 + 16) < K;
        if (more) TC_LD(k0 + 16);
#pragma unroll
        for (int ks = 0; ks < 16; ks += 8) {
            unsigned af[4][4], bf[4][2];
#pragma unroll
            for (int mf = 0; mf < 4; mf++) {
                int mb = wm + mf * 16 + g;
                af[mf][0] = As[ks + tid4][mb];
                af[mf][1] = As[ks + tid4][mb + 8];
                af[mf][2] = As[ks + tid4 + 4][mb];
                af[mf][3] = As[ks + tid4 + 4][mb + 8];
            }
#pragma unroll
            for (int nf = 0; nf < 4; nf++) {
                int nb = wn + nf * 8 + g;
                bf[nf][0] = Bs[ks + tid4][nb];
                bf[nf][1] = Bs[ks + tid4 + 4][nb];
            }
#pragma unroll
            for (int mf = 0; mf < 4; mf++)
#pragma unroll
                for (int nf = 0; nf < 4; nf++) {
                    asm volatile(
                        "mma.sync.aligned.m16n8k8.row.col.f32.tf32.tf32.f32 "
                        "{%0,%1,%2,%3}, {%4,%5,%6,%7}, {%8,%9}, {%0,%1,%2,%3};"
                        : "+f"(acc[mf][nf][0]), "+f"(acc[mf][nf][1]),
                          "+f"(acc[mf][nf][2]), "+f"(acc[mf][nf][3])
                        : "r"(af[mf][0]), "r"(af[mf][1]), "r"(af[mf][2]), "r"(af[mf][3]),
                          "r"(bf[nf][0]), "r"(bf[nf][1]));
                }
        }
        __syncthreads();
        if (more) { TC_ST(); __syncthreads(); }
    }

    if (C) {
        float* Cb = C + blockIdx.z * sC;
#pragma unroll
        for (int mf = 0; mf < 4; mf++) {
#pragma unroll
            for (int nf = 0; nf < 4; nf++) {
                size_t r0 = (size_t)(row0 + wm + mf * 16 + g);
                int c = col0 + wn + nf * 8 + tid4 * 2;
                *(float2*)&Cb[r0 * N + c]       = make_float2(acc[mf][nf][0], acc[mf][nf][1]);
                *(float2*)&Cb[(r0 + 8) * N + c] = make_float2(acc[mf][nf][2], acc[mf][nf][3]);
            }
        }
    }

    if (mxp) {
        int s = (col0 + wn) >> 5;
#pragma unroll
        for (int mf = 0; mf < 4; mf++) {
            float M0 = -1e30f, m0 = 1e30f, M1 = -1e30f, m1 = 1e30f;
#pragma unroll
            for (int nf = 0; nf < 4; nf++) {
                M0 = fmaxf(M0, fmaxf(acc[mf][nf][0], acc[mf][nf][1]));
                m0 = fminf(m0, fminf(acc[mf][nf][0], acc[mf][nf][1]));
                M1 = fmaxf(M1, fmaxf(acc[mf][nf][2], acc[mf][nf][3]));
                m1 = fminf(m1, fminf(acc[mf][nf][2], acc[mf][nf][3]));
            }
            M0 = fmaxf(M0, __shfl_xor_sync(~0u, M0, 1)); M0 = fmaxf(M0, __shfl_xor_sync(~0u, M0, 2));
            m0 = fminf(m0, __shfl_xor_sync(~0u, m0, 1)); m0 = fminf(m0, __shfl_xor_sync(~0u, m0, 2));
            M1 = fmaxf(M1, __shfl_xor_sync(~0u, M1, 1)); M1 = fmaxf(M1, __shfl_xor_sync(~0u, M1, 2));
            m1 = fminf(m1, __shfl_xor_sync(~0u, m1, 1)); m1 = fminf(m1, __shfl_xor_sync(~0u, m1, 2));
            if (tid4 == 0) {
                int r = row0 + wm + mf * 16 + g;
                size_t o1 = ((size_t)blockIdx.z * M + r) * (N >> 5) + s;
                size_t o2 = ((size_t)blockIdx.z * M + r + 8) * (N >> 5) + s;
                mxp[o1] = M0; mnp[o1] = m0;
                mxp[o2] = M1; mnp[o2] = m1;
            }
        }
    }

    if (bnp_sum) {
#pragma unroll
        for (int mf = 0; mf < 4; mf++) {
            float s0 = 0.f, q0 = 0.f, s1 = 0.f, q1 = 0.f;
#pragma unroll
            for (int nf = 0; nf < 4; nf++) {
                float a = acc[mf][nf][0], b = acc[mf][nf][1];
                float c = acc[mf][nf][2], d = acc[mf][nf][3];
                s0 += a + b; q0 += a * a + b * b;
                s1 += c + d; q1 += c * c + d * d;
            }
            s0 += __shfl_xor_sync(~0u, s0, 1); s0 += __shfl_xor_sync(~0u, s0, 2);
            q0 += __shfl_xor_sync(~0u, q0, 1); q0 += __shfl_xor_sync(~0u, q0, 2);
            s1 += __shfl_xor_sync(~0u, s1, 1); s1 += __shfl_xor_sync(~0u, s1, 2);
            q1 += __shfl_xor_sync(~0u, q1, 1); q1 += __shfl_xor_sync(~0u, q1, 2);
            if (tid4 == 0) {
                ssum[wid][mf * 16 + g] = s0;     ssq[wid][mf * 16 + g] = q0;
                ssum[wid][mf * 16 + g + 8] = s1; ssq[wid][mf * 16 + g + 8] = q1;
            }
        }
        __syncthreads();
        if (t < 128) {
            int half = t >> 6, lr = t & 63;
            float s = ssum[half * 4 + 0][lr] + ssum[half * 4 + 1][lr]
                    + ssum[half * 4 + 2][lr] + ssum[half * 4 + 3][lr];
            float q = ssq[half * 4 + 0][lr] + ssq[half * 4 + 1][lr]
                    + ssq[half * 4 + 2][lr] + ssq[half * 4 + 3][lr];
            int ch = row0 + t;
            int slot = (int)(blockIdx.z * gridDim.x + blockIdx.x);
            bnp_sum[(size_t)ch * 2048 + slot] = s;
            bnp_sq [(size_t)ch * 2048 + slot] = q;
        }
    }
}

// ---------------- softmax (fused BN2 affine) ----------------
__global__ void k_softmax(const float* __restrict__ g2, const float* __restrict__ b2) {
    int row = blockIdx.x;
    int s = row & (NP - 1);
    float mch = g_bnm[s], rch = g_bnr[s] * g2[s], bch = b2[s];
    float* x = g_h2 + (size_t)row * NN;
    int t = threadIdx.x;
    __shared__ float rs[256], rq[256];
    float m = -1e30f;
    for (int j = t; j < NN; j += 256) {
        float v = (x[j] - mch) * rch + bch;
        m = fmaxf(m, v);
    }
    rs[t] = m; __syncthreads();
    for (int o = 128; o > 0; o >>= 1) { if (t < o) rs[t] = fmaxf(rs[t], rs[t + o]); __syncthreads(); }
    m = rs[0]; __syncthreads();
    float ssum = 0.f, sq = 0.f;
    for (int j = t; j < NN; j += 256) {
        float v = (x[j] - mch) * rch + bch;
        float e = expf(v - m);
        x[j] = e;
        ssum += e; sq = fmaf(e, e, sq);
    }
    rs[t] = ssum; rq[t] = sq; __syncthreads();
    for (int o = 128; o > 0; o >>= 1) { if (t < o) { rs[t] += rs[t + o]; rq[t] += rq[t + o]; } __syncthreads(); }
    ssum = rs[0]; sq = rq[0];
    float inv = 1.f / ssum;
    for (int j = t; j < NN; j += 256) x[j] *= inv;
    if (t == 0) g_norm[row] = sqrtf(sq) * inv;
}

// ---------------- argmax + unique ----------------
__global__ void k_argmax() {
    int sidx = blockIdx.x;
    const float* x = g_h2 + (size_t)sidx * NN;
    int t = threadIdx.x;
    float bv = -1e30f; int bi = NN;
    for (int j = t; j < NN; j += 256) { float v = x[j]; if (v > bv) { bv = v; bi = j; } }
    __shared__ float rv[256]; __shared__ int ri[256];
    rv[t] = bv; ri[t] = bi; __syncthreads();
    for (int o = 128; o > 0; o >>= 1) {
        if (t < o) {
            if (rv[t + o] > rv[t] || (rv[t + o] == rv[t] && ri[t + o] < ri[t])) {
                rv[t] = rv[t + o]; ri[t] = ri[t + o];
            }
        }
        __syncthreads();
    }
    if (t == 0) g_amax[sidx] = ri[0];
}

__global__ void k_unique(float* __restrict__ out, int out_size) {
    __shared__ int fl[NN];
    __shared__ int rc[256];
    int t = threadIdx.x;
    for (int j = t; j < NN; j += 256) fl[j] = 0;
    __syncthreads();
    for (int s = t; s < NP; s += 256) fl[g_amax[s]] = 1;
    __syncthreads();
    int c = 0;
    for (int j = t; j < NN; j += 256) c += fl[j];
    rc[t] = c; __syncthreads();
    for (int o = 128; o > 0; o >>= 1) { if (t < o) rc[t] += rc[t + o]; __syncthreads(); }
    if (t == 0 && OUT_UNIQ < out_size) out[OUT_UNIQ] = (float)rc[0];
}

// ---------------- cos loss (upper triangle only, x2) ----------------
__global__ void k_loss() {
    int b = blockIdx.x;
    int t = threadIdx.x;
    const float* inn = g_inner + (size_t)b * NP * NP;
    const float* nrm = g_norm + b * NP;
    float s = 0.f;
    for (int i = t; i < NP * NP; i += 256) {
        int ss = i >> 9, tt = i & (NP - 1);
        if (tt <= ss) continue;
        float v = inn[i] / (nrm[ss] * nrm[tt] + 1e-10f);
        s = fmaf(2.f * v, v, s);
    }
    __shared__ float red[256];
    red[t] = s; __syncthreads();
    for (int o = 128; o > 0; o >>= 1) { if (t < o) red[t] += red[t + o]; __syncthreads(); }
    if (t == 0) g_losspart[b] = red[0];
}

__global__ void k_lossfin(float* __restrict__ out, int out_size) {
    if (threadIdx.x == 0 && OUT_LOSS < out_size) {
        float acc = 0.f;
        for (int b = 0; b < BB; b++) acc += sqrtf(g_losspart[b]);
        out[OUT_LOSS] = acc / (float)BB;
    }
}

// ---------------- weight prep ----------------
__global__ void k_w2p(const float* __restrict__ w2) {
    int i = blockIdx.x * blockDim.x + threadIdx.x;
    if (i >= NP * 80) return;
    int o = i / 80, c = i % 80;
    g_w2p[i] = (c < SCC) ? w2[o * SCC + c] : 0.f;
}

__global__ void k_padw(const float* __restrict__ w) {
    int i = blockIdx.x * blockDim.x + threadIdx.x;
    if (i >= 128 * 144) return;
    int o = i / 144, ch = i % 144;
    const float* wr = w + o * 134;
    float v = 0.f;
    if (ch < 64)       v = wr[64 + ch];
    else if (ch < 67)  v = wr[131 + (ch - 64)];
    else if (ch == 67) v = 0.f;
    else if (ch < 132) { int c = ch - 68;  v = wr[c] - wr[64 + c]; }
    else if (ch < 135) { int c = ch - 132; v = wr[128 + c] - wr[131 + c]; }
    g_w0p[i] = v;
}

// ---------------- final: BN + leaky on max/min, pick true max ----------------
__global__ void k_bn_max(const float* __restrict__ g2, const float* __restrict__ b2,
                         float* __restrict__ out, int out_size) {
    int i = blockIdx.x * blockDim.x + threadIdx.x;
    if (i >= BB * 256 * NP) return;
    int o = (i / NP) % 256;
    float mch = g_bnm[o], rch = g_bnr[o] * g2[o], bch = b2[o];
    float v1 = (g_mx[i] - mch) * rch + bch;
    float v2 = (g_mn[i] - mch) * rch + bch;
    v1 = v1 > 0.f ? v1 : 0.2f * v1;
    v2 = v2 > 0.f ? v2 : 0.2f * v2;
    int oi = OUT_PTS + i;
    if (oi < out_size) out[oi] = fmaxf(v1, v2);
}

__global__ void k_wxyz(float* __restrict__ out, int out_size) {
    int i = blockIdx.x * blockDim.x + threadIdx.x;
    if (i >= BB * 3 * NP) return;
    int s = i % NP; int c = (i / NP) % 3; int b = i / (3 * NP);
    if (i < out_size) out[i] = g_spx[((size_t)b * NP + s) * GPX_N + AGG0 + 64 + c];
}

// ---------------- launch ----------------
extern "C" void kernel_launch(void* const* d_in, const int* in_sizes, int n_in,
                              void* d_out, int out_size) {
    const float* xyz   = (const float*)d_in[0];
    const float* pts   = (const float*)d_in[1];
    const float* w1_w  = (const float*)d_in[2];
    const float* bn1_g = (const float*)d_in[4];
    const float* bn1_b = (const float*)d_in[5];
    const float* w2_w  = (const float*)d_in[6];
    const float* bn2_g = (const float*)d_in[8];
    const float* bn2_b = (const float*)d_in[9];
    const float* c0w   = (const float*)d_in[10];
    const float* bg0   = (const float*)d_in[12];
    const float* bb0   = (const float*)d_in[13];
    const float* c1w   = (const float*)d_in[14];
    const float* bg1   = (const float*)d_in[16];
    const float* bb1   = (const float*)d_in[17];
    const float* c2w   = (const float*)d_in[18];
    const float* bg2   = (const float*)d_in[20];
    const float* bb2   = (const float*)d_in[21];
    float* out = (float*)d_out;

    float *p_agg, *p_h1, *p_h2, *p_w2p, *p_spx, *p_inner, *p_w0p,
          *p_c0, *p_c1, *p_mx, *p_mn, *p_bnm, *p_bnr, *p_bps, *p_bpq;
    int* p_idx;
    cudaGetSymbolAddress((void**)&p_agg,   g_agg);
    cudaGetSymbolAddress((void**)&p_idx,   g_idx);
    cudaGetSymbolAddress((void**)&p_h1,    g_h1);
    cudaGetSymbolAddress((void**)&p_h2,    g_h2);
    cudaGetSymbolAddress((void**)&p_w2p,   g_w2p);
    cudaGetSymbolAddress((void**)&p_spx,   g_spx);
    cudaGetSymbolAddress((void**)&p_inner, g_inner);
    cudaGetSymbolAddress((void**)&p_w0p,   g_w0p);
    cudaGetSymbolAddress((void**)&p_c0,    g_c0);
    cudaGetSymbolAddress((void**)&p_c1,    g_c1);
    cudaGetSymbolAddress((void**)&p_mx,    g_mx);
    cudaGetSymbolAddress((void**)&p_mn,    g_mn);
    cudaGetSymbolAddress((void**)&p_bnm,   g_bnm);
    cudaGetSymbolAddress((void**)&p_bnr,   g_bnr);
    cudaGetSymbolAddress((void**)&p_bps,   g_bnp_sum);
    cudaGetSymbolAddress((void**)&p_bpq,   g_bnp_sq);

    k_prep<<<(BB * NN + 255) / 256, 256>>>(xyz, pts);
    k_ballquery<<<dim3(NN / 256, BB), 256>>>();
    k_h1<<<dim3(NN / 256, SCC, BB), 256>>>(w1_w);
    k_bnstats<<<SCC, 256>>>(p_h1, SCC, 80, NN);
    k_w2p<<<(NP * 80 + 255) / 256, 256>>>(w2_w);
    // h2 = w2p @ bn1(h1)  (TC tf32, K=80, BN on B; stats epilogue for bn2)
    k_gemm_tc<<<dim3(16, 4, BB), 256>>>(
        p_w2p, p_h1, p_h2, NP, NN, 80,
        0, (size_t)80 * NN, (size_t)NP * NN,
        0, 0, 0, p_idx, p_agg,
        p_bnm, p_bnr, bn1_g, bn1_b, SCC, 0,
        p_bps, p_bpq, nullptr, nullptr);
    k_bnfin<<<NP, 256>>>(BB * 16, (float)BB * NN);
    k_softmax<<<BB * NP, 256>>>(bn2_g, bn2_b);
    k_argmax<<<NP, 256>>>();
    k_unique<<<1, 256>>>(out, out_size);
    // inner = sel @ sel^T  (TC NT, upper-tri 128x128 blocks)
    k_gemm_tc<<<dim3(10, 1, BB), 256>>>(
        p_h2, p_h2, p_inner, NP, NP, NN,
        (size_t)NP * NN, (size_t)NP * NN, (size_t)NP * NP,
        0, 1, 1, p_idx, p_agg,
        nullptr, nullptr, nullptr, nullptr, 0, 0,
        nullptr, nullptr, nullptr, nullptr);
    k_loss<<<BB, 256>>>();
    k_lossfin<<<1, 1>>>(out, out_size);
    // spx = sel @ gather(agg)  (TC mode2)
    k_gemm_tc<<<dim3(GPX_N / 128, 4, BB), 256>>>(
        p_h2, nullptr, p_spx, NP, GPX_N, NN,
        (size_t)NP * NN, 0, (size_t)NP * GPX_N,
        2, 0, 0, p_idx, p_agg,
        nullptr, nullptr, nullptr, nullptr, 0, 0,
        nullptr, nullptr, nullptr, nullptr);
    k_padw<<<(128 * 144 + 255) / 256, 256>>>(c0w);
    // conv0  (TC mode3: edge synthesized from spx; stats epilogue)
    k_gemm_tc<<<dim3(KS / 128, 1, BB), 256>>>(
        p_w0p, p_spx, p_c0, 128, KS, 144,
        0, (size_t)NP * GPX_N, (size_t)128 * KS,
        3, 0, 0, p_idx, p_agg,
        nullptr, nullptr, nullptr, nullptr, 0, 0,
        p_bps, p_bpq, nullptr, nullptr);
    k_bnfin<<<128, 256>>>(BB * (KS / 128), (float)BB * KS);
    // conv1 (BN0+leaky fused on B, stats epilogue)
    k_gemm_tc<<<dim3(KS / 128, 1, BB), 256>>>(
        c1w, p_c0, p_c1, 128, KS, 128,
        0, (size_t)128 * KS, (size_t)128 * KS,
        0, 0, 0, p_idx, p_agg,
        p_bnm, p_bnr, bg0, bb0, 128, 1,
        p_bps, p_bpq, nullptr, nullptr);
    k_bnfin<<<128, 256>>>(BB * (KS / 128), (float)BB * KS);
    // conv2 (BN1+leaky fused on B, stats + maxmin epilogues, no C store)
    k_gemm_tc<<<dim3(KS / 128, 2, BB), 256>>>(
        c2w, p_c1, nullptr, 256, KS, 128,
        0, (size_t)128 * KS, 0,
        0, 0, 0, p_idx, p_agg,
        p_bnm, p_bnr, bg1, bb1, 128, 1,
        p_bps, p_bpq, p_mx, p_mn);
    k_bnfin<<<256, 256>>>(BB * (KS / 128), (float)BB * KS);
    k_bn_max<<<(BB * 256 * NP + 255) / 256, 256>>>(bg2, bb2, out, out_size);
    k_wxyz<<<(BB * 3 * NP + 255) / 256, 256>>>(out, out_size);
}